// round 2
// baseline (speedup 1.0000x reference)
#include <cuda_runtime.h>

typedef unsigned long long ull;

// ---------------- scratch (__device__ globals; no allocation) ----------------
__device__ float g_z1[1024 * 64 * 1024];   // conv1 output [img][oc][y][x]  (268MB)
__device__ float g_pool[1024 * 128];       // pooled conv2 features
__device__ float g_h[1024 * 256];          // fc output (masked) [b*32+n][256]
__device__ float g_out1[1024 * 256];       // sage1 output
__device__ float g_cs[2][32 * 256];        // per-batch column sums
__device__ float g_wc1[256 * 256];         // rw - lw/31 (layer 1)
__device__ float g_wc2[128 * 256];         // rw - lw/31 (layer 2)
__device__ float g_base1[32 * 256];        // colsum@lw/31 + lb (layer 1)
__device__ float g_base2[32 * 128];        // layer 2

// ---------------- f32x2 packed helpers (Blackwell) ----------------
__device__ __forceinline__ ull pk2(float v) {
    ull r; asm("mov.b64 %0, {%1, %2};" : "=l"(r) : "f"(v), "f"(v)); return r;
}
__device__ __forceinline__ ull ffma2(ull a, ull b, ull c) {
    ull d; asm("fma.rn.f32x2 %0, %1, %2, %3;" : "=l"(d) : "l"(a), "l"(b), "l"(c)); return d;
}
__device__ __forceinline__ float2 upk(ull v) {
    float2 f; asm("mov.b64 {%0, %1}, %2;" : "=f"(f.x), "=f"(f.y) : "l"(v)); return f;
}

// ---------------- conv1 (3->64, 3x3 SAME) + ReLU ----------------
// one block per image; thread t owns 4 horizontally-adjacent pixels (row t/8, cols (t%8)*4..+3)
__global__ __launch_bounds__(256) void conv1_kernel(const float* __restrict__ x,
                                                    const float* __restrict__ w,
                                                    const float* __restrict__ bias) {
    __shared__ float sIn[3 * 1024];
    __shared__ float sW[27 * 64];   // [ic*9+kt][oc]
    __shared__ float sB[64];
    int img = blockIdx.x, tid = threadIdx.x;
    for (int j = tid; j < 3072; j += 256) sIn[j] = x[img * 3072 + j];
    for (int e = tid; e < 1728; e += 256) { int k = e >> 6, o = e & 63; sW[e] = w[o * 27 + k]; }
    if (tid < 64) sB[tid] = bias[tid];
    __syncthreads();
    int r = tid >> 3, x0 = (tid & 7) << 2;
    for (int oc0 = 0; oc0 < 64; oc0 += 16) {
        float acc[4][16];
#pragma unroll
        for (int p = 0; p < 4; p++)
#pragma unroll
            for (int o = 0; o < 16; o++) acc[p][o] = sB[oc0 + o];
#pragma unroll
        for (int ic = 0; ic < 3; ic++) {
#pragma unroll
            for (int ky = 0; ky < 3; ky++) {
                int yy = r + ky - 1;
                float iv[6];
                if ((unsigned)yy < 32u) {
                    const float* row = sIn + ic * 1024 + yy * 32;
#pragma unroll
                    for (int j = 0; j < 6; j++) {
                        int xx = x0 - 1 + j;
                        iv[j] = ((unsigned)xx < 32u) ? row[xx] : 0.f;
                    }
                } else {
#pragma unroll
                    for (int j = 0; j < 6; j++) iv[j] = 0.f;
                }
#pragma unroll
                for (int kx = 0; kx < 3; kx++) {
                    const float* wp = sW + (ic * 9 + ky * 3 + kx) * 64 + oc0;
                    float wv[16];
#pragma unroll
                    for (int o = 0; o < 16; o++) wv[o] = wp[o];
#pragma unroll
                    for (int p = 0; p < 4; p++) {
                        float v = iv[p + kx];
#pragma unroll
                        for (int o = 0; o < 16; o++) acc[p][o] = fmaf(v, wv[o], acc[p][o]);
                    }
                }
            }
        }
        float* dst = g_z1 + (size_t)img * 65536 + (size_t)oc0 * 1024 + tid * 4;
#pragma unroll
        for (int o = 0; o < 16; o++) {
            float4 v = make_float4(fmaxf(acc[0][o], 0.f), fmaxf(acc[1][o], 0.f),
                                   fmaxf(acc[2][o], 0.f), fmaxf(acc[3][o], 0.f));
            *reinterpret_cast<float4*>(dst + o * 1024) = v;
        }
    }
}

// ---------------- conv2 (64->128) + ReLU + global mean pool, fused ----------------
// grid (1024 images, 8 oc-groups of 16); f32x2 packed FMA on oc pairs.
__global__ __launch_bounds__(256) void conv2_pool_kernel(const float* __restrict__ w,
                                                         const float* __restrict__ bias) {
    extern __shared__ float smem[];
    float* sIn  = smem;            // 16 ic * 1024 px = 16384 floats
    float* sW   = smem + 16384;    // 144 * 16 floats  (pairs of adjacent oc -> ull)
    float* sRed = sW + 2304;       // 8 warps * 16
    int img = blockIdx.x;
    int oc0 = blockIdx.y * 16;
    int tid = threadIdx.x;
    int r = tid >> 3, x0 = (tid & 7) << 2;
    ull z = pk2(0.f);
    ull acc[4][8];
#pragma unroll
    for (int p = 0; p < 4; p++)
#pragma unroll
        for (int j = 0; j < 8; j++) acc[p][j] = z;

    for (int ic0 = 0; ic0 < 64; ic0 += 16) {
        __syncthreads();
        const float4* src = reinterpret_cast<const float4*>(g_z1 + (size_t)img * 65536 + (size_t)ic0 * 1024);
        float4* d4 = reinterpret_cast<float4*>(sIn);
#pragma unroll
        for (int j = 0; j < 16; j++) d4[tid + j * 256] = src[tid + j * 256];
        for (int e = tid; e < 2304; e += 256) {
            int k = e >> 4, o = e & 15, ic_l = k / 9, kt = k % 9;
            sW[e] = w[(oc0 + o) * 576 + (ic0 + ic_l) * 9 + kt];
        }
        __syncthreads();
        for (int ic = 0; ic < 16; ic++) {
            const float* in = sIn + ic * 1024;
#pragma unroll
            for (int ky = 0; ky < 3; ky++) {
                int yy = r + ky - 1;
                ull iv2[6];
                if ((unsigned)yy < 32u) {
                    const float* row = in + yy * 32;
#pragma unroll
                    for (int j = 0; j < 6; j++) {
                        int xx = x0 - 1 + j;
                        iv2[j] = pk2(((unsigned)xx < 32u) ? row[xx] : 0.f);
                    }
                } else {
#pragma unroll
                    for (int j = 0; j < 6; j++) iv2[j] = z;
                }
#pragma unroll
                for (int kx = 0; kx < 3; kx++) {
                    const ull* wp = reinterpret_cast<const ull*>(sW + (ic * 9 + ky * 3 + kx) * 16);
                    ull wr[8];
#pragma unroll
                    for (int j = 0; j < 8; j++) wr[j] = wp[j];
#pragma unroll
                    for (int p = 0; p < 4; p++) {
                        ull v = iv2[p + kx];
#pragma unroll
                        for (int j = 0; j < 8; j++) acc[p][j] = ffma2(v, wr[j], acc[p][j]);
                    }
                }
            }
        }
    }
    // bias + relu + local pool over the thread's 4 pixels
    float s[16];
#pragma unroll
    for (int j = 0; j < 8; j++) {
        float b0 = bias[oc0 + 2 * j], b1 = bias[oc0 + 2 * j + 1];
        float s0 = 0.f, s1 = 0.f;
#pragma unroll
        for (int p = 0; p < 4; p++) {
            float2 f = upk(acc[p][j]);
            s0 += fmaxf(f.x + b0, 0.f);
            s1 += fmaxf(f.y + b1, 0.f);
        }
        s[2 * j] = s0; s[2 * j + 1] = s1;
    }
#pragma unroll
    for (int off = 16; off > 0; off >>= 1)
#pragma unroll
        for (int o = 0; o < 16; o++) s[o] += __shfl_xor_sync(0xffffffffu, s[o], off);
    int lane = tid & 31, warp = tid >> 5;
    __syncthreads();
    if (lane == 0) {
#pragma unroll
        for (int o = 0; o < 16; o++) sRed[warp * 16 + o] = s[o];
    }
    __syncthreads();
    if (tid < 16) {
        float t = 0.f;
#pragma unroll
        for (int wv = 0; wv < 8; wv++) t += sRed[wv * 16 + tid];
        g_pool[img * 128 + oc0 + tid] = t * (1.f / 1024.f);
    }
}

// ---------------- FC 128->256 + mask ----------------
__global__ __launch_bounds__(256) void fc_kernel(const float* __restrict__ fw,
                                                 const float* __restrict__ fb,
                                                 const float* __restrict__ mask) {
    __shared__ float sP[128];
    int i = blockIdx.x, o = threadIdx.x;
    if (o < 128) sP[o] = g_pool[i * 128 + o];
    __syncthreads();
    float acc = fb[o];
    const float4* w4 = reinterpret_cast<const float4*>(fw + o * 128);
    const float4* p4 = reinterpret_cast<const float4*>(sP);
    float s = 0.f;
#pragma unroll 8
    for (int k = 0; k < 32; k++) {
        float4 wv = w4[k], pv = p4[k];
        s = fmaf(wv.x, pv.x, s); s = fmaf(wv.y, pv.y, s);
        s = fmaf(wv.z, pv.z, s); s = fmaf(wv.w, pv.w, s);
    }
    g_h[i * 256 + o] = (acc + s) * mask[i];
}

// ---------------- per-batch column sums over nodes ----------------
__global__ void colsum_kernel(int layer) {
    int b = blockIdx.x, d = threadIdx.x;
    const float* src = layer ? g_out1 : g_h;
    float s = 0.f;
#pragma unroll 8
    for (int n = 0; n < 32; n++) s += src[(b * 32 + n) * 256 + d];
    g_cs[layer][b * 256 + d] = s;
}

// ---------------- combined weight: rw - lw/31 ----------------
__global__ void wcomb_kernel(const float* __restrict__ lw, const float* __restrict__ rw, int layer) {
    int e = blockIdx.x * 256 + threadIdx.x;
    float* dst = layer ? g_wc2 : g_wc1;
    dst[e] = rw[e] - lw[e] * (1.f / 31.f);
}

// ---------------- base: lb + colsum@lw/31 ----------------
__global__ void base_kernel(const float* __restrict__ lw, const float* __restrict__ lb, int layer) {
    int b = blockIdx.x, o = threadIdx.x;
    const float* csr = g_cs[layer] + b * 256;
    const float* wr = lw + o * 256;
    float s = 0.f;
#pragma unroll 8
    for (int d = 0; d < 256; d++) s = fmaf(csr[d], wr[d], s);
    float* dst = layer ? g_base2 : g_base1;
    dst[b * (int)blockDim.x + o] = lb[o] + s * (1.f / 31.f);
}

// ---------------- node GEMM: out = base + h @ wcomb^T (+ relu for layer 1) ----------------
__global__ void sage_gemm_kernel(int layer, float* __restrict__ dout) {
    __shared__ float sH[256];
    int i = blockIdx.x, o = threadIdx.x, b = i >> 5;
    int O = blockDim.x;
    const float* hin = layer ? g_out1 : g_h;
    const float* wc  = layer ? g_wc2 : g_wc1;
    const float* base = layer ? g_base2 : g_base1;
    for (int j = o; j < 256; j += O) sH[j] = hin[i * 256 + j];
    __syncthreads();
    float acc = base[b * O + o];
    const float4* w4 = reinterpret_cast<const float4*>(wc + o * 256);
    const float4* h4 = reinterpret_cast<const float4*>(sH);
    float s = 0.f;
#pragma unroll 8
    for (int k = 0; k < 64; k++) {
        float4 wv = w4[k], hv = h4[k];
        s = fmaf(wv.x, hv.x, s); s = fmaf(wv.y, hv.y, s);
        s = fmaf(wv.z, hv.z, s); s = fmaf(wv.w, hv.w, s);
    }
    acc += s;
    if (!layer) acc = fmaxf(acc, 0.f);
    float* out = layer ? dout : g_out1;
    out[i * O + o] = acc;
}

// ---------------- launch ----------------
extern "C" void kernel_launch(void* const* d_in, const int* in_sizes, int n_in,
                              void* d_out, int out_size) {
    const float* x       = (const float*)d_in[0];
    const float* mask    = (const float*)d_in[1];
    const float* conv1_w = (const float*)d_in[2];
    const float* conv1_b = (const float*)d_in[3];
    const float* conv2_w = (const float*)d_in[4];
    const float* conv2_b = (const float*)d_in[5];
    const float* fc_w    = (const float*)d_in[6];
    const float* fc_b    = (const float*)d_in[7];
    const float* s1_lw   = (const float*)d_in[8];
    const float* s1_lb   = (const float*)d_in[9];
    const float* s1_rw   = (const float*)d_in[10];
    const float* s2_lw   = (const float*)d_in[11];
    const float* s2_lb   = (const float*)d_in[12];
    const float* s2_rw   = (const float*)d_in[13];
    float* out = (float*)d_out;

    const int SMEM2 = (16384 + 2304 + 128) * 4;  // 75264 bytes
    cudaFuncSetAttribute(conv2_pool_kernel, cudaFuncAttributeMaxDynamicSharedMemorySize, SMEM2);

    conv1_kernel<<<1024, 256>>>(x, conv1_w, conv1_b);
    conv2_pool_kernel<<<dim3(1024, 8), 256, SMEM2>>>(conv2_w, conv2_b);
    fc_kernel<<<1024, 256>>>(fc_w, fc_b, mask);

    colsum_kernel<<<32, 256>>>(0);
    wcomb_kernel<<<256, 256>>>(s1_lw, s1_rw, 0);
    base_kernel<<<32, 256>>>(s1_lw, s1_lb, 0);
    sage_gemm_kernel<<<1024, 256>>>(0, out);

    colsum_kernel<<<32, 256>>>(1);
    wcomb_kernel<<<128, 256>>>(s2_lw, s2_rw, 1);
    base_kernel<<<32, 128>>>(s2_lw, s2_lb, 1);
    sage_gemm_kernel<<<1024, 128>>>(1, out);
}

// round 6
// speedup vs baseline: 5.8252x; 5.8252x over previous
#include <cuda_runtime.h>
#include <cuda_bf16.h>
#include <cstdint>

// ---------------- scratch (__device__ globals; no allocation) ----------------
__device__ uint32_t g_a32[1024 * 32768];   // conv1 output NHWC bf16 pairs (134MB)
__device__ float g_pool[1024 * 128];
__device__ float g_h[1024 * 256];
__device__ float g_out1[1024 * 256];
__device__ float g_cs[2][32 * 256];
__device__ float g_wc1[256 * 256];
__device__ float g_wc2[128 * 256];
__device__ float g_base1[32 * 256];
__device__ float g_base2[32 * 128];

// ---------------- helpers ----------------
__device__ __forceinline__ uint32_t smem_u32(const void* p) {
    uint32_t a;
    asm("{ .reg .u64 t; cvta.to.shared.u64 t, %1; cvt.u32.u64 %0, t; }" : "=r"(a) : "l"(p));
    return a;
}
__device__ __forceinline__ uint32_t pack_bf2(float a, float b) {
    __nv_bfloat162 t = __floats2bfloat162_rn(a, b);
    return *reinterpret_cast<uint32_t*>(&t);
}
__device__ __forceinline__ void ldmx4(uint32_t& r0, uint32_t& r1, uint32_t& r2, uint32_t& r3,
                                      uint32_t addr) {
    asm volatile("ldmatrix.sync.aligned.m8n8.x4.shared.b16 {%0,%1,%2,%3}, [%4];"
                 : "=r"(r0), "=r"(r1), "=r"(r2), "=r"(r3) : "r"(addr));
}
__device__ __forceinline__ void mma16816(float* c, uint32_t a0, uint32_t a1, uint32_t a2,
                                         uint32_t a3, uint32_t b0, uint32_t b1) {
    asm volatile(
        "mma.sync.aligned.m16n8k16.row.col.f32.bf16.bf16.f32 "
        "{%0,%1,%2,%3}, {%4,%5,%6,%7}, {%8,%9}, {%0,%1,%2,%3};"
        : "+f"(c[0]), "+f"(c[1]), "+f"(c[2]), "+f"(c[3])
        : "r"(a0), "r"(a1), "r"(a2), "r"(a3), "r"(b0), "r"(b1));
}

// ---------------- conv1 (3->64, 3x3 SAME) + ReLU -> NHWC bf16 ----------------
__global__ __launch_bounds__(256) void conv1_kernel(const float* __restrict__ x,
                                                    const float* __restrict__ w,
                                                    const float* __restrict__ bias) {
    __shared__ float sIn[3 * 1024];
    __shared__ float sW[27 * 64];
    __shared__ float sB[64];
    int img = blockIdx.x, tid = threadIdx.x;
    for (int j = tid; j < 3072; j += 256) sIn[j] = x[img * 3072 + j];
    for (int e = tid; e < 1728; e += 256) { int k = e >> 6, o = e & 63; sW[e] = w[o * 27 + k]; }
    if (tid < 64) sB[tid] = bias[tid];
    __syncthreads();
    int r = tid >> 3, x0 = (tid & 7) << 2;
    for (int oc0 = 0; oc0 < 64; oc0 += 16) {
        float acc[4][16];
#pragma unroll
        for (int p = 0; p < 4; p++)
#pragma unroll
            for (int o = 0; o < 16; o++) acc[p][o] = sB[oc0 + o];
#pragma unroll
        for (int ic = 0; ic < 3; ic++) {
#pragma unroll
            for (int ky = 0; ky < 3; ky++) {
                int yy = r + ky - 1;
                float iv[6];
                if ((unsigned)yy < 32u) {
                    const float* row = sIn + ic * 1024 + yy * 32;
#pragma unroll
                    for (int j = 0; j < 6; j++) {
                        int xx = x0 - 1 + j;
                        iv[j] = ((unsigned)xx < 32u) ? row[xx] : 0.f;
                    }
                } else {
#pragma unroll
                    for (int j = 0; j < 6; j++) iv[j] = 0.f;
                }
#pragma unroll
                for (int kx = 0; kx < 3; kx++) {
                    const float* wp = sW + (ic * 9 + ky * 3 + kx) * 64 + oc0;
                    float wv[16];
#pragma unroll
                    for (int o = 0; o < 16; o++) wv[o] = wp[o];
#pragma unroll
                    for (int p = 0; p < 4; p++) {
                        float v = iv[p + kx];
#pragma unroll
                        for (int o = 0; o < 16; o++) acc[p][o] = fmaf(v, wv[o], acc[p][o]);
                    }
                }
            }
        }
#pragma unroll
        for (int p = 0; p < 4; p++) {
            int pix = r * 32 + x0 + p;
            uint32_t* dst = g_a32 + (size_t)img * 32768 + pix * 32 + (oc0 >> 1);
#pragma unroll
            for (int oo = 0; oo < 8; oo++)
                dst[oo] = pack_bf2(fmaxf(acc[p][2 * oo], 0.f), fmaxf(acc[p][2 * oo + 1], 0.f));
        }
    }
}

// ---------------- conv2 via mma.sync bf16 (hi/lo weight split) + ReLU + pool ----------------
// SMEM: B (hi+lo) 149504 | A tile 48960 | bias 256 | pool 2048  => 200768 bytes
static constexpr int B_OFF = 0;
static constexpr int B_HL = 74752;        // bytes per weight plane (64 n x 584 k x 2B)
static constexpr int SIN_OFF = 149504;    // 10 rows x 34 px x 72 el x 2B
static constexpr int SBIAS_OFF = 198464;
static constexpr int SPOOL_OFF = 198720;  // 16 warps x 32 floats
static constexpr int SMEM2_TOTAL = 200768;

__global__ __launch_bounds__(512, 1) void conv2_mma_kernel(const float* __restrict__ w,
                                                           const float* __restrict__ bias) {
    extern __shared__ __align__(16) char smem[];
    uint32_t sbase = smem_u32(smem);
    float* sBias = reinterpret_cast<float*>(smem + SBIAS_OFF);
    float* sPool = reinterpret_cast<float*>(smem + SPOOL_OFF);
    int tid = threadIdx.x, lane = tid & 31, wid = tid >> 5;
    int m_idx = wid & 7, n_idx = wid >> 3;

    // zero x-halo pixels (smem px cols 0 and 33), rows 0..9, ch words 0..31
    for (int e = tid; e < 640; e += 512) {
        int r = e >> 6, side = (e >> 5) & 1, q = e & 31;
        int px = side ? 33 : 0;
        *reinterpret_cast<uint32_t*>(smem + SIN_OFF + r * 4896 + px * 144 + q * 4) = 0u;
    }

    // per-thread ldmatrix address components
    uint32_t aThr = (uint32_t)((lane & 15) * 144 + ((lane >> 4) & 1) * 16);
    uint32_t bThr = (uint32_t)(((((lane >> 4) & 1) * 8 + (lane & 7)) * 584 +
                                ((lane >> 3) & 1) * 8) * 2 + n_idx * 37376);

    for (int half = 0; half < 2; half++) {
        int ocg = half * 64;
        __syncthreads();
        // build B hi/lo: sB[n][k], k = s*64 + ic, k-stride padded to 584 elems
        for (int e = tid; e < 36864; e += 512) {
            int n = e / 576, k = e - n * 576;
            int ic = k & 63, s = k >> 6;
            float v = w[(ocg + n) * 576 + ic * 9 + s];
            __nv_bfloat16 hi = __float2bfloat16(v);
            __nv_bfloat16 lo = __float2bfloat16(v - __bfloat162float(hi));
            int off = (n * 584 + k) * 2;
            *reinterpret_cast<__nv_bfloat16*>(smem + B_OFF + off) = hi;
            *reinterpret_cast<__nv_bfloat16*>(smem + B_OFF + B_HL + off) = lo;
        }
        if (tid < 64) sBias[tid] = bias[ocg + tid];
        __syncthreads();
        float bv[4][2];
#pragma unroll
        for (int f = 0; f < 4; f++) {
            bv[f][0] = sBias[n_idx * 32 + f * 8 + (lane & 3) * 2];
            bv[f][1] = sBias[n_idx * 32 + f * 8 + (lane & 3) * 2 + 1];
        }

        for (int img = blockIdx.x; img < 1024; img += gridDim.x) {
            const uint32_t* gsrc = g_a32 + (size_t)img * 32768;
            float pool[4][2];
#pragma unroll
            for (int f = 0; f < 4; f++) { pool[f][0] = 0.f; pool[f][1] = 0.f; }

            for (int t = 0; t < 4; t++) {
                __syncthreads();  // previous tile's reads done before overwrite
                // load 10 rows (8 + 2 halo) via cp.async, zero-fill out-of-range rows
#pragma unroll
                for (int i = 0; i < 5; i++) {
                    int c = tid + i * 512;
                    int wr = c >> 8, rem = c & 255;
                    int px = rem >> 3, q = rem & 7;
                    int gy = t * 8 + wr - 1;
                    uint32_t ok = ((unsigned)gy < 32u) ? 16u : 0u;
                    int gyc = gy < 0 ? 0 : (gy > 31 ? 31 : gy);
                    const void* g = gsrc + gyc * 1024 + px * 32 + q * 4;
                    uint32_t sd = sbase + SIN_OFF + (uint32_t)(wr * 4896 + (px + 1) * 144 + q * 16);
                    asm volatile("cp.async.cg.shared.global [%0], [%1], 16, %2;"
                                 :: "r"(sd), "l"(g), "r"(ok) : "memory");
                }
                asm volatile("cp.async.commit_group;" ::: "memory");
                asm volatile("cp.async.wait_group 0;" ::: "memory");
                __syncthreads();

                float acc[2][4][4];
#pragma unroll
                for (int fm = 0; fm < 2; fm++)
#pragma unroll
                    for (int f = 0; f < 4; f++)
#pragma unroll
                        for (int j = 0; j < 4; j++) acc[fm][f][j] = 0.f;

                uint32_t aBase = sbase + SIN_OFF + (uint32_t)(m_idx * 4896) + aThr;
                uint32_t bBase = sbase + B_OFF + bThr;
#pragma unroll
                for (int s = 0; s < 9; s++) {
                    const uint32_t doff = (uint32_t)(((s / 3) * 34 + (s % 3)) * 144);
#pragma unroll
                    for (int ks = 0; ks < 4; ks++) {
                        uint32_t a0, a1, a2, a3, a4, a5, a6, a7;
                        ldmx4(a0, a1, a2, a3, aBase + doff + ks * 32);
                        ldmx4(a4, a5, a6, a7, aBase + doff + 2304 + ks * 32);
                        uint32_t kofs = (uint32_t)(s * 128 + ks * 32);
#pragma unroll
                        for (int fp = 0; fp < 2; fp++) {
#pragma unroll
                            for (int hl = 0; hl < 2; hl++) {
                                uint32_t r0, r1, r2, r3;
                                ldmx4(r0, r1, r2, r3,
                                      bBase + (uint32_t)(fp * 18688 + hl * 74752) + kofs);
                                mma16816(acc[0][fp * 2], a0, a1, a2, a3, r0, r1);
                                mma16816(acc[1][fp * 2], a4, a5, a6, a7, r0, r1);
                                mma16816(acc[0][fp * 2 + 1], a0, a1, a2, a3, r2, r3);
                                mma16816(acc[1][fp * 2 + 1], a4, a5, a6, a7, r2, r3);
                            }
                        }
                    }
                }
                // bias + relu + pixel-pool (rows held by this thread)
#pragma unroll
                for (int fm = 0; fm < 2; fm++)
#pragma unroll
                    for (int f = 0; f < 4; f++) {
                        pool[f][0] += fmaxf(acc[fm][f][0] + bv[f][0], 0.f) +
                                      fmaxf(acc[fm][f][2] + bv[f][0], 0.f);
                        pool[f][1] += fmaxf(acc[fm][f][1] + bv[f][1], 0.f) +
                                      fmaxf(acc[fm][f][3] + bv[f][1], 0.f);
                    }
            }
            // reduce over lanes with same (lane&3): xor bits 2..4
#pragma unroll
            for (int off = 4; off <= 16; off <<= 1)
#pragma unroll
                for (int f = 0; f < 4; f++) {
                    pool[f][0] += __shfl_xor_sync(0xffffffffu, pool[f][0], off);
                    pool[f][1] += __shfl_xor_sync(0xffffffffu, pool[f][1], off);
                }
            if (lane < 4) {
                float* sp = sPool + wid * 32;
#pragma unroll
                for (int f = 0; f < 4; f++) {
                    sp[f * 8 + lane * 2] = pool[f][0];
                    sp[f * 8 + lane * 2 + 1] = pool[f][1];
                }
            }
            __syncthreads();
            if (tid < 64) {
                int ni = tid >> 5, col = tid & 31;
                float s = 0.f;
#pragma unroll
                for (int m = 0; m < 8; m++) s += sPool[(ni * 8 + m) * 32 + col];
                g_pool[img * 128 + ocg + ni * 32 + col] = s * (1.f / 1024.f);
            }
        }
    }
}

// ---------------- FC 128->256 + mask ----------------
__global__ __launch_bounds__(256) void fc_kernel(const float* __restrict__ fw,
                                                 const float* __restrict__ fb,
                                                 const float* __restrict__ mask) {
    __shared__ float sP[128];
    int i = blockIdx.x, o = threadIdx.x;
    if (o < 128) sP[o] = g_pool[i * 128 + o];
    __syncthreads();
    float acc = fb[o];
    const float4* w4 = reinterpret_cast<const float4*>(fw + o * 128);
    const float4* p4 = reinterpret_cast<const float4*>(sP);
    float s = 0.f;
#pragma unroll 8
    for (int k = 0; k < 32; k++) {
        float4 wv = w4[k], pv = p4[k];
        s = fmaf(wv.x, pv.x, s); s = fmaf(wv.y, pv.y, s);
        s = fmaf(wv.z, pv.z, s); s = fmaf(wv.w, pv.w, s);
    }
    g_h[i * 256 + o] = (acc + s) * mask[i];
}

// ---------------- per-batch column sums ----------------
__global__ void colsum_kernel(int layer) {
    int b = blockIdx.x, d = threadIdx.x;
    const float* src = layer ? g_out1 : g_h;
    float s = 0.f;
#pragma unroll 8
    for (int n = 0; n < 32; n++) s += src[(b * 32 + n) * 256 + d];
    g_cs[layer][b * 256 + d] = s;
}

// ---------------- combined weight: rw - lw/31 ----------------
__global__ void wcomb_kernel(const float* __restrict__ lw, const float* __restrict__ rw, int layer) {
    int e = blockIdx.x * 256 + threadIdx.x;
    float* dst = layer ? g_wc2 : g_wc1;
    dst[e] = rw[e] - lw[e] * (1.f / 31.f);
}

// ---------------- base: lb + colsum@lw/31 ----------------
__global__ void base_kernel(const float* __restrict__ lw, const float* __restrict__ lb, int layer) {
    int b = blockIdx.x, o = threadIdx.x;
    const float* csr = g_cs[layer] + b * 256;
    const float* wr = lw + o * 256;
    float s = 0.f;
#pragma unroll 8
    for (int d = 0; d < 256; d++) s = fmaf(csr[d], wr[d], s);
    float* dst = layer ? g_base2 : g_base1;
    dst[b * (int)blockDim.x + o] = lb[o] + s * (1.f / 31.f);
}

// ---------------- node GEMM: out = base + h @ wcomb^T (+ relu for layer 1) ----------------
__global__ void sage_gemm_kernel(int layer, float* __restrict__ dout) {
    __shared__ float sH[256];
    int i = blockIdx.x, o = threadIdx.x, b = i >> 5;
    int O = blockDim.x;
    const float* hin = layer ? g_out1 : g_h;
    const float* wc  = layer ? g_wc2 : g_wc1;
    const float* base = layer ? g_base2 : g_base1;
    for (int j = o; j < 256; j += O) sH[j] = hin[i * 256 + j];
    __syncthreads();
    float acc = base[b * O + o];
    const float4* w4 = reinterpret_cast<const float4*>(wc + o * 256);
    const float4* h4 = reinterpret_cast<const float4*>(sH);
    float s = 0.f;
#pragma unroll 8
    for (int k = 0; k < 64; k++) {
        float4 wv = w4[k], hv = h4[k];
        s = fmaf(wv.x, hv.x, s); s = fmaf(wv.y, hv.y, s);
        s = fmaf(wv.z, hv.z, s); s = fmaf(wv.w, hv.w, s);
    }
    acc += s;
    if (!layer) acc = fmaxf(acc, 0.f);
    float* out = layer ? dout : g_out1;
    out[i * O + o] = acc;
}

// ---------------- launch ----------------
extern "C" void kernel_launch(void* const* d_in, const int* in_sizes, int n_in,
                              void* d_out, int out_size) {
    const float* x       = (const float*)d_in[0];
    const float* mask    = (const float*)d_in[1];
    const float* conv1_w = (const float*)d_in[2];
    const float* conv1_b = (const float*)d_in[3];
    const float* conv2_w = (const float*)d_in[4];
    const float* conv2_b = (const float*)d_in[5];
    const float* fc_w    = (const float*)d_in[6];
    const float* fc_b    = (const float*)d_in[7];
    const float* s1_lw   = (const float*)d_in[8];
    const float* s1_lb   = (const float*)d_in[9];
    const float* s1_rw   = (const float*)d_in[10];
    const float* s2_lw   = (const float*)d_in[11];
    const float* s2_lb   = (const float*)d_in[12];
    const float* s2_rw   = (const float*)d_in[13];
    float* out = (float*)d_out;

    cudaFuncSetAttribute(conv2_mma_kernel, cudaFuncAttributeMaxDynamicSharedMemorySize,
                         SMEM2_TOTAL);

    conv1_kernel<<<1024, 256>>>(x, conv1_w, conv1_b);
    conv2_mma_kernel<<<148, 512, SMEM2_TOTAL>>>(conv2_w, conv2_b);
    fc_kernel<<<1024, 256>>>(fc_w, fc_b, mask);

    colsum_kernel<<<32, 256>>>(0);
    wcomb_kernel<<<256, 256>>>(s1_lw, s1_rw, 0);
    base_kernel<<<32, 256>>>(s1_lw, s1_lb, 0);
    sage_gemm_kernel<<<1024, 256>>>(0, out);

    colsum_kernel<<<32, 256>>>(1);
    wcomb_kernel<<<128, 256>>>(s2_lw, s2_rw, 1);
    base_kernel<<<32, 128>>>(s2_lw, s2_lb, 1);
    sage_gemm_kernel<<<1024, 128>>>(1, out);
}

// round 7
// speedup vs baseline: 8.8103x; 1.5125x over previous
#include <cuda_runtime.h>
#include <cuda_fp16.h>
#include <cstdint>

// ---------------- scratch (__device__ globals; no allocation) ----------------
__device__ uint32_t g_a32[1024 * 32768];   // conv1 output NHWC fp16 pairs (134MB)
__device__ float g_pool[1024 * 128];       // pooled conv2 features

// ---------------- helpers ----------------
__device__ __forceinline__ uint32_t smem_u32(const void* p) {
    uint32_t a;
    asm("{ .reg .u64 t; cvta.to.shared.u64 t, %1; cvt.u32.u64 %0, t; }" : "=r"(a) : "l"(p));
    return a;
}
__device__ __forceinline__ uint32_t pack_h2(float a, float b) {
    __half2 t = __floats2half2_rn(a, b);
    return *reinterpret_cast<uint32_t*>(&t);
}
__device__ __forceinline__ void ldmx4(uint32_t& r0, uint32_t& r1, uint32_t& r2, uint32_t& r3,
                                      uint32_t addr) {
    asm volatile("ldmatrix.sync.aligned.m8n8.x4.shared.b16 {%0,%1,%2,%3}, [%4];"
                 : "=r"(r0), "=r"(r1), "=r"(r2), "=r"(r3) : "r"(addr));
}
__device__ __forceinline__ void mma16816(float* c, const uint32_t* a, uint32_t b0, uint32_t b1) {
    asm volatile(
        "mma.sync.aligned.m16n8k16.row.col.f32.f16.f16.f32 "
        "{%0,%1,%2,%3}, {%4,%5,%6,%7}, {%8,%9}, {%0,%1,%2,%3};"
        : "+f"(c[0]), "+f"(c[1]), "+f"(c[2]), "+f"(c[3])
        : "r"(a[0]), "r"(a[1]), "r"(a[2]), "r"(a[3]), "r"(b0), "r"(b1));
}

// ---------------- conv1 (3->64, 3x3 SAME) + ReLU -> NHWC fp16 ----------------
__global__ __launch_bounds__(256) void conv1_kernel(const float* __restrict__ x,
                                                    const float* __restrict__ w,
                                                    const float* __restrict__ bias) {
    __shared__ float sIn[3 * 1024];
    __shared__ float sW[27 * 64];
    __shared__ float sB[64];
    int img = blockIdx.x, tid = threadIdx.x;
    for (int j = tid; j < 3072; j += 256) sIn[j] = x[img * 3072 + j];
    for (int e = tid; e < 1728; e += 256) { int k = e >> 6, o = e & 63; sW[e] = w[o * 27 + k]; }
    if (tid < 64) sB[tid] = bias[tid];
    __syncthreads();
    int r = tid >> 3, x0 = (tid & 7) << 2;
    for (int oc0 = 0; oc0 < 64; oc0 += 16) {
        float acc[4][16];
#pragma unroll
        for (int p = 0; p < 4; p++)
#pragma unroll
            for (int o = 0; o < 16; o++) acc[p][o] = sB[oc0 + o];
#pragma unroll
        for (int ic = 0; ic < 3; ic++) {
#pragma unroll
            for (int ky = 0; ky < 3; ky++) {
                int yy = r + ky - 1;
                float iv[6];
                if ((unsigned)yy < 32u) {
                    const float* row = sIn + ic * 1024 + yy * 32;
#pragma unroll
                    for (int j = 0; j < 6; j++) {
                        int xx = x0 - 1 + j;
                        iv[j] = ((unsigned)xx < 32u) ? row[xx] : 0.f;
                    }
                } else {
#pragma unroll
                    for (int j = 0; j < 6; j++) iv[j] = 0.f;
                }
#pragma unroll
                for (int kx = 0; kx < 3; kx++) {
                    const float* wp = sW + (ic * 9 + ky * 3 + kx) * 64 + oc0;
                    float wv[16];
#pragma unroll
                    for (int o = 0; o < 16; o++) wv[o] = wp[o];
#pragma unroll
                    for (int p = 0; p < 4; p++) {
                        float v = iv[p + kx];
#pragma unroll
                        for (int o = 0; o < 16; o++) acc[p][o] = fmaf(v, wv[o], acc[p][o]);
                    }
                }
            }
        }
#pragma unroll
        for (int p = 0; p < 4; p++) {
            int pix = r * 32 + x0 + p;
            uint32_t* dst = g_a32 + (size_t)img * 32768 + pix * 32 + (oc0 >> 1);
#pragma unroll
            for (int oo = 0; oo < 8; oo++)
                dst[oo] = pack_h2(fmaxf(acc[p][2 * oo], 0.f), fmaxf(acc[p][2 * oo + 1], 0.f));
        }
    }
}

// ---------------- conv2 via mma.sync fp16 (all 128 oc resident) + ReLU + pool ----------------
// SMEM: B 149504 | A tile 48960 | bias 512 | pool 2048 => 201024 bytes
static constexpr int B_OFF = 0;           // 128 n x 584 k x 2B
static constexpr int SIN_OFF = 149504;    // 10 rows x 34 px x 72 el x 2B
static constexpr int SBIAS_OFF = 198464;  // 128 f32
static constexpr int SPOOL_OFF = 198976;  // 16 warps x 32 f32
static constexpr int SMEM2_TOTAL = 201024;

__global__ __launch_bounds__(512, 1) void conv2_mma_kernel(const float* __restrict__ w,
                                                           const float* __restrict__ bias) {
    extern __shared__ __align__(16) char smem[];
    uint32_t sbase = smem_u32(smem);
    float* sBias = reinterpret_cast<float*>(smem + SBIAS_OFF);
    float* sPool = reinterpret_cast<float*>(smem + SPOOL_OFF);
    int tid = threadIdx.x, lane = tid & 31, wid = tid >> 5;
    int m_idx = wid & 3, n_idx = wid >> 2;   // 4 m-warps (64px each) x 4 n-warps (32oc each)

    // zero x-halo pixels (smem px cols 0 and 33), rows 0..9
    for (int e = tid; e < 640; e += 512) {
        int r = e >> 6, side = (e >> 5) & 1, q = e & 31;
        int px = side ? 33 : 0;
        *reinterpret_cast<uint32_t*>(smem + SIN_OFF + r * 4896 + px * 144 + q * 4) = 0u;
    }
    // build B: sB[n][k], k = s*64 + ic, k-stride padded to 584 elems (fp16, no hi/lo)
    for (int e = tid; e < 73728; e += 512) {
        int n = e / 576, k = e - n * 576;
        int ic = k & 63, s = k >> 6;
        float v = w[n * 576 + ic * 9 + s];
        *reinterpret_cast<__half*>(smem + B_OFF + (n * 584 + k) * 2) = __float2half(v);
    }
    if (tid < 128) sBias[tid] = bias[tid];
    __syncthreads();

    // per-thread ldmatrix address components
    uint32_t aThr = (uint32_t)((lane & 15) * 144 + ((lane >> 4) & 1) * 16);
    uint32_t bThr = (uint32_t)(((((lane >> 4) & 1) * 8 + (lane & 7)) * 584 +
                                ((lane >> 3) & 1) * 8) * 2 + n_idx * 37376);
    float bv[4][2];
#pragma unroll
    for (int j = 0; j < 4; j++) {
        bv[j][0] = sBias[n_idx * 32 + j * 8 + (lane & 3) * 2];
        bv[j][1] = sBias[n_idx * 32 + j * 8 + (lane & 3) * 2 + 1];
    }
    // A fragment row offsets: 4 m16 frags -> 2 image rows per warp
    uint32_t fragOff[4];
#pragma unroll
    for (int f = 0; f < 4; f++)
        fragOff[f] = (uint32_t)((2 * m_idx + (f >> 1)) * 4896 + (f & 1) * 16 * 144);

    for (int img = blockIdx.x; img < 1024; img += gridDim.x) {
        const uint32_t* gsrc = g_a32 + (size_t)img * 32768;
        float pool[4][2];
#pragma unroll
        for (int j = 0; j < 4; j++) { pool[j][0] = 0.f; pool[j][1] = 0.f; }

        for (int t = 0; t < 4; t++) {
            __syncthreads();  // previous tile's reads done before overwrite
#pragma unroll
            for (int i = 0; i < 5; i++) {
                int c = tid + i * 512;
                int wr = c >> 8, rem = c & 255;
                int px = rem >> 3, q = rem & 7;
                int gy = t * 8 + wr - 1;
                uint32_t ok = ((unsigned)gy < 32u) ? 16u : 0u;
                int gyc = gy < 0 ? 0 : (gy > 31 ? 31 : gy);
                const void* g = gsrc + gyc * 1024 + px * 32 + q * 4;
                uint32_t sd = sbase + SIN_OFF + (uint32_t)(wr * 4896 + (px + 1) * 144 + q * 16);
                asm volatile("cp.async.cg.shared.global [%0], [%1], 16, %2;"
                             :: "r"(sd), "l"(g), "r"(ok) : "memory");
            }
            asm volatile("cp.async.commit_group;" ::: "memory");
            asm volatile("cp.async.wait_group 0;" ::: "memory");
            __syncthreads();

            float acc[4][4][4];
#pragma unroll
            for (int f = 0; f < 4; f++)
#pragma unroll
                for (int j = 0; j < 4; j++)
#pragma unroll
                    for (int q = 0; q < 4; q++) acc[f][j][q] = 0.f;

            uint32_t aBase = sbase + SIN_OFF + aThr;
            uint32_t bBase = sbase + B_OFF + bThr;
#pragma unroll
            for (int s = 0; s < 9; s++) {
                const uint32_t doff = (uint32_t)(((s / 3) * 34 + (s % 3)) * 144);
#pragma unroll
                for (int ks = 0; ks < 4; ks++) {
                    uint32_t a[4][4];
#pragma unroll
                    for (int f = 0; f < 4; f++)
                        ldmx4(a[f][0], a[f][1], a[f][2], a[f][3],
                              aBase + fragOff[f] + doff + ks * 32);
                    uint32_t kofs = (uint32_t)(s * 128 + ks * 32);
#pragma unroll
                    for (int fp = 0; fp < 2; fp++) {
                        uint32_t r0, r1, r2, r3;
                        ldmx4(r0, r1, r2, r3, bBase + (uint32_t)(fp * 18688) + kofs);
#pragma unroll
                        for (int f = 0; f < 4; f++) {
                            mma16816(acc[f][fp * 2], a[f], r0, r1);
                            mma16816(acc[f][fp * 2 + 1], a[f], r2, r3);
                        }
                    }
                }
            }
            // bias + relu + pixel-pool
#pragma unroll
            for (int f = 0; f < 4; f++)
#pragma unroll
                for (int j = 0; j < 4; j++) {
                    pool[j][0] += fmaxf(acc[f][j][0] + bv[j][0], 0.f) +
                                  fmaxf(acc[f][j][2] + bv[j][0], 0.f);
                    pool[j][1] += fmaxf(acc[f][j][1] + bv[j][1], 0.f) +
                                  fmaxf(acc[f][j][3] + bv[j][1], 0.f);
                }
        }
        // reduce over lanes with same (lane&3)
#pragma unroll
        for (int off = 4; off <= 16; off <<= 1)
#pragma unroll
            for (int j = 0; j < 4; j++) {
                pool[j][0] += __shfl_xor_sync(0xffffffffu, pool[j][0], off);
                pool[j][1] += __shfl_xor_sync(0xffffffffu, pool[j][1], off);
            }
        if (lane < 4) {
            float* sp = sPool + wid * 32;
#pragma unroll
            for (int j = 0; j < 4; j++) {
                sp[j * 8 + lane * 2] = pool[j][0];
                sp[j * 8 + lane * 2 + 1] = pool[j][1];
            }
        }
        __syncthreads();
        if (tid < 128) {
            int ni = tid >> 5, col = tid & 31;
            float s = 0.f;
#pragma unroll
            for (int m = 0; m < 4; m++) s += sPool[(ni * 4 + m) * 32 + col];
            g_pool[img * 128 + tid] = s * (1.f / 1024.f);
        }
    }
}

// ---------------- fused tail: fc + mask + colsum + sage1 + colsum + sage2 ----------------
// one block per batch (32 nodes). dynamic smem, float offsets:
static constexpr int TP_POOL = 0;       // 32 x 128
static constexpr int TP_H    = 4096;    // 32 x 256 (reused as sage2 partials)
static constexpr int TP_O1   = 12288;   // 32 x 256
static constexpr int TP_CS   = 20480;   // 256
static constexpr int TP_B2   = 20736;   // 256
static constexpr int TP_MASK = 20992;   // 32
static constexpr int TAIL_SMEM = 21024 * 4;

__global__ __launch_bounds__(256) void tail_kernel(
    const float* __restrict__ fc_w, const float* __restrict__ fc_b,
    const float* __restrict__ mask,
    const float* __restrict__ s1_lw, const float* __restrict__ s1_lb,
    const float* __restrict__ s1_rw,
    const float* __restrict__ s2_lw, const float* __restrict__ s2_lb,
    const float* __restrict__ s2_rw,
    float* __restrict__ out) {
    extern __shared__ float sm[];
    float* sPool = sm + TP_POOL;
    float* sH    = sm + TP_H;
    float* sO1   = sm + TP_O1;
    float* sCs   = sm + TP_CS;
    float* sB2   = sm + TP_B2;
    float* sMask = sm + TP_MASK;
    int b = blockIdx.x, tid = threadIdx.x;

    for (int e = tid; e < 4096; e += 256) sPool[e] = g_pool[b * 4096 + e];
    if (tid < 32) sMask[tid] = mask[b * 32 + tid];
    __syncthreads();

    // fc: thread = output dim o (256); 32 nodes in registers
    {
        float acc[32];
#pragma unroll
        for (int n = 0; n < 32; n++) acc[n] = 0.f;
        const float4* wrow = reinterpret_cast<const float4*>(fc_w + tid * 128);
#pragma unroll 4
        for (int k4 = 0; k4 < 32; k4++) {
            float4 wv = wrow[k4];
#pragma unroll
            for (int n = 0; n < 32; n++) {
                float4 hv = *reinterpret_cast<const float4*>(sPool + n * 128 + k4 * 4);
                acc[n] += wv.x * hv.x + wv.y * hv.y + wv.z * hv.z + wv.w * hv.w;
            }
        }
        float fb = fc_b[tid];
#pragma unroll
        for (int n = 0; n < 32; n++) sH[n * 256 + tid] = (acc[n] + fb) * sMask[n];
    }
    __syncthreads();
    {
        float s = 0.f;
#pragma unroll
        for (int n = 0; n < 32; n++) s += sH[n * 256 + tid];
        sCs[tid] = s;
    }
    __syncthreads();

    // sage1: thread = o (256), combined weight computed on the fly
    {
        float acc[32];
#pragma unroll
        for (int n = 0; n < 32; n++) acc[n] = 0.f;
        float bacc = 0.f;
        const float4* lw4 = reinterpret_cast<const float4*>(s1_lw + tid * 256);
        const float4* rw4 = reinterpret_cast<const float4*>(s1_rw + tid * 256);
#pragma unroll 2
        for (int k4 = 0; k4 < 64; k4++) {
            float4 lw = lw4[k4], rw = rw4[k4];
            float4 cs = *reinterpret_cast<const float4*>(sCs + k4 * 4);
            bacc += cs.x * lw.x + cs.y * lw.y + cs.z * lw.z + cs.w * lw.w;
            float4 wc;
            wc.x = rw.x - lw.x * (1.f / 31.f); wc.y = rw.y - lw.y * (1.f / 31.f);
            wc.z = rw.z - lw.z * (1.f / 31.f); wc.w = rw.w - lw.w * (1.f / 31.f);
#pragma unroll
            for (int n = 0; n < 32; n++) {
                float4 hv = *reinterpret_cast<const float4*>(sH + n * 256 + k4 * 4);
                acc[n] += wc.x * hv.x + wc.y * hv.y + wc.z * hv.z + wc.w * hv.w;
            }
        }
        float base = s1_lb[tid] + bacc * (1.f / 31.f);
#pragma unroll
        for (int n = 0; n < 32; n++) sO1[n * 256 + tid] = fmaxf(base + acc[n], 0.f);
    }
    __syncthreads();
    {
        float s = 0.f;
#pragma unroll
        for (int n = 0; n < 32; n++) s += sO1[n * 256 + tid];
        sCs[tid] = s;
    }
    __syncthreads();

    // sage2: o2 = tid&127, k-half = tid>>7; partials into sH (free now)
    {
        int o2 = tid & 127, half = tid >> 7;
        float acc[32];
#pragma unroll
        for (int n = 0; n < 32; n++) acc[n] = 0.f;
        float bacc = 0.f;
        const float4* lw4 = reinterpret_cast<const float4*>(s2_lw + o2 * 256 + half * 128);
        const float4* rw4 = reinterpret_cast<const float4*>(s2_rw + o2 * 256 + half * 128);
        const float* csb = sCs + half * 128;
        const float* o1b = sO1 + half * 128;
#pragma unroll 2
        for (int k4 = 0; k4 < 32; k4++) {
            float4 lw = lw4[k4], rw = rw4[k4];
            float4 cs = *reinterpret_cast<const float4*>(csb + k4 * 4);
            bacc += cs.x * lw.x + cs.y * lw.y + cs.z * lw.z + cs.w * lw.w;
            float4 wc;
            wc.x = rw.x - lw.x * (1.f / 31.f); wc.y = rw.y - lw.y * (1.f / 31.f);
            wc.z = rw.z - lw.z * (1.f / 31.f); wc.w = rw.w - lw.w * (1.f / 31.f);
#pragma unroll
            for (int n = 0; n < 32; n++) {
                float4 hv = *reinterpret_cast<const float4*>(o1b + n * 256 + k4 * 4);
                acc[n] += wc.x * hv.x + wc.y * hv.y + wc.z * hv.z + wc.w * hv.w;
            }
        }
#pragma unroll
        for (int n = 0; n < 32; n++) sH[n * 256 + tid] = acc[n];
        sB2[tid] = bacc;
    }
    __syncthreads();
    for (int e = tid; e < 4096; e += 256) {
        int n = e >> 7, o2 = e & 127;
        float v = sH[n * 256 + o2] + sH[n * 256 + o2 + 128];
        float base = s2_lb[o2] + (sB2[o2] + sB2[o2 + 128]) * (1.f / 31.f);
        out[(b * 32 + n) * 128 + o2] = base + v;
    }
}

// ---------------- launch ----------------
extern "C" void kernel_launch(void* const* d_in, const int* in_sizes, int n_in,
                              void* d_out, int out_size) {
    const float* x       = (const float*)d_in[0];
    const float* mask    = (const float*)d_in[1];
    const float* conv1_w = (const float*)d_in[2];
    const float* conv1_b = (const float*)d_in[3];
    const float* conv2_w = (const float*)d_in[4];
    const float* conv2_b = (const float*)d_in[5];
    const float* fc_w    = (const float*)d_in[6];
    const float* fc_b    = (const float*)d_in[7];
    const float* s1_lw   = (const float*)d_in[8];
    const float* s1_lb   = (const float*)d_in[9];
    const float* s1_rw   = (const float*)d_in[10];
    const float* s2_lw   = (const float*)d_in[11];
    const float* s2_lb   = (const float*)d_in[12];
    const float* s2_rw   = (const float*)d_in[13];
    float* out = (float*)d_out;

    cudaFuncSetAttribute(conv2_mma_kernel, cudaFuncAttributeMaxDynamicSharedMemorySize,
                         SMEM2_TOTAL);
    cudaFuncSetAttribute(tail_kernel, cudaFuncAttributeMaxDynamicSharedMemorySize,
                         TAIL_SMEM);

    conv1_kernel<<<1024, 256>>>(x, conv1_w, conv1_b);
    conv2_mma_kernel<<<148, 512, SMEM2_TOTAL>>>(conv2_w, conv2_b);
    tail_kernel<<<32, 256, TAIL_SMEM>>>(fc_w, fc_b, mask, s1_lw, s1_lb, s1_rw,
                                        s2_lw, s2_lb, s2_rw, out);
}